// round 11
// baseline (speedup 1.0000x reference)
#include <cuda_runtime.h>
#include <cstdint>

// Problem dims
#define NB 32
#define C  64
#define H  128
#define W  128
#define CO 64
#define HO 64
#define WO 64

// Packed weight sign bits: g_wpack[co*9 + ky*3 + kx]
__device__ uint64_t g_wpack[CO * 9];

// ---------------------------------------------------------------------------
// Kernel 1: pack w sign bits (tiny; 16 blocks x 36 words).
// ---------------------------------------------------------------------------
__global__ __launch_bounds__(64) void pack_w_kernel(const float* __restrict__ w) {
    int t = blockIdx.x * 36 + threadIdx.x;
    if (threadIdx.x < 36 && t < CO * 9) {
        int co = t / 9;
        int k  = t - co * 9;
        uint32_t lo = 0, hi = 0;
        #pragma unroll 8
        for (int ci = 0; ci < 32; ++ci)
            lo |= (uint32_t)(w[(size_t)(co * 64 + ci) * 9 + k] >= 0.0f) << ci;
        #pragma unroll 8
        for (int ci = 0; ci < 32; ++ci)
            hi |= (uint32_t)(w[(size_t)(co * 64 + ci + 32) * 9 + k] >= 0.0f) << ci;
        g_wpack[t] = (uint64_t)lo | ((uint64_t)hi << 32);
    }
}

// ---------------------------------------------------------------------------
// Kernel 2: FUSED pack + conv, warp-specialized software pipeline.
// Grid (8, NB) = 256 blocks, 256 threads. Block owns 4 tiles (tile = 2
// output rows x 64 wo x 64 co), double-buffered 5x129-word patches.
//   warps 0-3 (128 thr): PRODUCERS — pack tile g+1's patch from x floats.
//   warps 4-7 (128 thr): CONSUMERS — compute tile g (1 pixel/thread, 64 co).
// One __syncthreads per tile. Mem latency of the next patch hides under the
// popcount compute of the current one, inside every block — breaks the
// global phase lockstep that serialized DRAM(30us) + ALU(27us) in R10.
// ---------------------------------------------------------------------------
__global__ __launch_bounds__(256) void qconv_pipe_kernel(const float* __restrict__ x,
                                                         float* __restrict__ out) {
    const int PW = 132;
    __shared__ uint64_t sw[CO * 9];            // 4608 B
    __shared__ uint64_t sp[2][5 * PW];         // 2 x 5280 B

    int tid = threadIdx.x;
    int n   = blockIdx.y;
    int ho0 = blockIdx.x * 8;                  // 4 tiles: rows ho0 .. ho0+7

    bool producer = (tid < 128);

    // ---- Prologue: producers pack tile 0; consumers stage weights ----
    if (producer) {
        int iy0 = 2 * ho0 - 1;
        for (int i = tid; i < 5 * 129; i += 128) {
            int r  = i / 129;
            int cx = i - r * 129;
            int iy = iy0 + r;
            int ix = cx - 1;
            uint32_t lo = 0, hi = 0;
            if (iy >= 0 && ix >= 0) {
                const float* p = x + (size_t)n * C * (H * W) + iy * W + ix;
                #pragma unroll 16
                for (int c = 0; c < 32; ++c) {
                    lo |= (uint32_t)(__ldcs(p + (size_t)c * (H * W)) >= 0.0f) << c;
                    hi |= (uint32_t)(__ldcs(p + (size_t)(c + 32) * (H * W)) >= 0.0f) << c;
                }
            }
            sp[0][r * PW + cx] = (uint64_t)lo | ((uint64_t)hi << 32);
        }
    } else {
        for (int i = tid - 128; i < CO * 9; i += 128)
            sw[i] = g_wpack[i];
    }
    __syncthreads();

    // ---- Pipelined tiles ----
    #pragma unroll 1
    for (int g = 0; g < 4; ++g) {
        if (producer) {
            // Pack tile g+1 into the other buffer (skip after last tile)
            if (g < 3) {
                int hog = ho0 + 2 * (g + 1);
                int iy0 = 2 * hog - 1;
                uint64_t* buf = sp[(g + 1) & 1];
                for (int i = tid; i < 5 * 129; i += 128) {
                    int r  = i / 129;
                    int cx = i - r * 129;
                    int iy = iy0 + r;
                    int ix = cx - 1;
                    uint32_t lo = 0, hi = 0;
                    if (ix >= 0) {             // iy >= 1 always for g >= 1
                        const float* p = x + (size_t)n * C * (H * W) + iy * W + ix;
                        #pragma unroll 16
                        for (int c = 0; c < 32; ++c) {
                            lo |= (uint32_t)(__ldcs(p + (size_t)c * (H * W)) >= 0.0f) << c;
                            hi |= (uint32_t)(__ldcs(p + (size_t)(c + 32) * (H * W)) >= 0.0f) << c;
                        }
                    }
                    buf[r * PW + cx] = (uint64_t)lo | ((uint64_t)hi << 32);
                }
            }
        } else {
            // Compute tile g from buffer g&1
            const uint64_t* buf = sp[g & 1];
            int cid = tid - 128;
            int tx  = cid & 63;                // wo
            int q   = cid >> 6;                // 0..1
            int ho  = ho0 + 2 * g + q;

            uint32_t slo[9], shi[9];
            #pragma unroll
            for (int ky = 0; ky < 3; ++ky) {
                #pragma unroll
                for (int kx = 0; kx < 3; ++kx) {
                    int t = ky * 3 + kx;
                    uint64_t s = buf[(2 * q + ky) * PW + 2 * tx + kx];
                    slo[t] = (uint32_t)s;
                    shi[t] = (uint32_t)(s >> 32);
                }
            }
            uint32_t mr = (ho > 0) ? 0xFFFFFFFFu : 0u;
            uint32_t mc = (tx > 0) ? 0xFFFFFFFFu : 0u;
            uint32_t mb = mr & mc;
            int base = 64 * (ho > 0 ? 3 : 2) * (tx > 0 ? 3 : 2);

            float* op = out + (((size_t)n * CO) * HO + ho) * WO + tx;

            #pragma unroll 4
            for (int co = 0; co < CO; ++co) {
                const uint64_t* wrow = sw + co * 9;
                int acc = 0;
                #pragma unroll
                for (int t = 0; t < 9; ++t) {
                    uint64_t wv = wrow[t];     // warp-uniform broadcast LDS
                    uint32_t wl = (uint32_t)wv;
                    uint32_t wh = (uint32_t)(wv >> 32);
                    if (t == 0) {
                        acc += __popc((slo[t] ^ wl) & mb);
                        acc += __popc((shi[t] ^ wh) & mb);
                    } else if (t == 1 || t == 2) {
                        acc += __popc((slo[t] ^ wl) & mr);
                        acc += __popc((shi[t] ^ wh) & mr);
                    } else if (t == 3 || t == 6) {
                        acc += __popc((slo[t] ^ wl) & mc);
                        acc += __popc((shi[t] ^ wh) & mc);
                    } else {
                        acc += __popc(slo[t] ^ wl);
                        acc += __popc(shi[t] ^ wh);
                    }
                }
                op[(size_t)co * (HO * WO)] = (float)(base - 2 * acc);
            }
        }
        __syncthreads();
    }
}

// ---------------------------------------------------------------------------
extern "C" void kernel_launch(void* const* d_in, const int* in_sizes, int n_in,
                              void* d_out, int out_size) {
    const float* x = (const float*)d_in[0];
    const float* w = (const float*)d_in[1];
    float* out = (float*)d_out;

    pack_w_kernel<<<16, 64>>>(w);
    qconv_pipe_kernel<<<dim3(8, NB), 256>>>(x, out);
}

// round 12
// speedup vs baseline: 1.0199x; 1.0199x over previous
#include <cuda_runtime.h>
#include <cstdint>

// Problem dims
#define NB 32
#define C  64
#define H  128
#define W  128
#define CO 64
#define HO 64
#define WO 64

// Packed weight sign bits: g_wpack[co*9 + ky*3 + kx]
__device__ uint64_t g_wpack[CO * 9];

// ---------------------------------------------------------------------------
// Kernel 1: pack w sign bits (tiny; 16 blocks x 36 words).
// ---------------------------------------------------------------------------
__global__ __launch_bounds__(64) void pack_w_kernel(const float* __restrict__ w) {
    int t = blockIdx.x * 36 + threadIdx.x;
    if (threadIdx.x < 36 && t < CO * 9) {
        int co = t / 9;
        int k  = t - co * 9;
        uint32_t lo = 0, hi = 0;
        #pragma unroll 8
        for (int ci = 0; ci < 32; ++ci)
            lo |= (uint32_t)(w[(size_t)(co * 64 + ci) * 9 + k] >= 0.0f) << ci;
        #pragma unroll 8
        for (int ci = 0; ci < 32; ++ci)
            hi |= (uint32_t)(w[(size_t)(co * 64 + ci + 32) * 9 + k] >= 0.0f) << ci;
        g_wpack[t] = (uint64_t)lo | ((uint64_t)hi << 32);
    }
}

// ---------------------------------------------------------------------------
// Kernel 2: FUSED pack + conv, warp-specialized pipeline — occupancy fixed.
// Grid (16, NB) = 512 blocks (3.46 resident/SM vs R11's 1.73), 256 threads.
// Block owns 2 tiles (tile = 2 output rows x 64 wo x 64 co), double-buffered
// 5x129-word patches.
//   warps 0-3: PRODUCERS — pack tile g+1's patch from x floats.
//   warps 4-7: CONSUMERS — compute tile g (1 pixel/thread, all 64 co).
// Per block: pack0 -> [pack1 || comp0] -> comp1. With ~14 producer warps/SM
// the DRAM stream runs near 5.6TB/s while ~14 consumer warps saturate the
// alu pipe — the overlap R10/R11 never achieved.
// ---------------------------------------------------------------------------
__global__ __launch_bounds__(256) void qconv_pipe_kernel(const float* __restrict__ x,
                                                         float* __restrict__ out) {
    const int PW = 132;
    __shared__ uint64_t sw[CO * 9];            // 4608 B
    __shared__ uint64_t sp[2][5 * PW];         // 2 x 5280 B

    int tid = threadIdx.x;
    int n   = blockIdx.y;
    int ho0 = blockIdx.x * 4;                  // 2 tiles: rows ho0 .. ho0+3

    bool producer = (tid < 128);

    // ---- Prologue: producers pack tile 0; consumers stage weights ----
    if (producer) {
        int iy0 = 2 * ho0 - 1;
        for (int i = tid; i < 5 * 129; i += 128) {
            int r  = i / 129;
            int cx = i - r * 129;
            int iy = iy0 + r;
            int ix = cx - 1;
            uint32_t lo = 0, hi = 0;
            if (iy >= 0 && ix >= 0) {
                const float* p = x + (size_t)n * C * (H * W) + iy * W + ix;
                #pragma unroll 16
                for (int c = 0; c < 32; ++c) {
                    lo |= (uint32_t)(__ldcs(p + (size_t)c * (H * W)) >= 0.0f) << c;
                    hi |= (uint32_t)(__ldcs(p + (size_t)(c + 32) * (H * W)) >= 0.0f) << c;
                }
            }
            sp[0][r * PW + cx] = (uint64_t)lo | ((uint64_t)hi << 32);
        }
    } else {
        for (int i = tid - 128; i < CO * 9; i += 128)
            sw[i] = g_wpack[i];
    }
    __syncthreads();

    // ---- Pipelined tiles ----
    #pragma unroll 1
    for (int g = 0; g < 2; ++g) {
        if (producer) {
            if (g < 1) {
                // Pack tile 1 (rows ho0+2, ho0+3): iy0 = 2*ho0+3 >= 3, no iy guard
                int iy0 = 2 * (ho0 + 2) - 1;
                uint64_t* buf = sp[1];
                for (int i = tid; i < 5 * 129; i += 128) {
                    int r  = i / 129;
                    int cx = i - r * 129;
                    int iy = iy0 + r;
                    int ix = cx - 1;
                    uint32_t lo = 0, hi = 0;
                    if (ix >= 0) {
                        const float* p = x + (size_t)n * C * (H * W) + iy * W + ix;
                        #pragma unroll 16
                        for (int c = 0; c < 32; ++c) {
                            lo |= (uint32_t)(__ldcs(p + (size_t)c * (H * W)) >= 0.0f) << c;
                            hi |= (uint32_t)(__ldcs(p + (size_t)(c + 32) * (H * W)) >= 0.0f) << c;
                        }
                    }
                    buf[r * PW + cx] = (uint64_t)lo | ((uint64_t)hi << 32);
                }
            }
        } else {
            // Compute tile g from buffer g
            const uint64_t* buf = sp[g];
            int cid = tid - 128;
            int tx  = cid & 63;                // wo
            int q   = cid >> 6;                // 0..1
            int ho  = ho0 + 2 * g + q;

            uint32_t slo[9], shi[9];
            #pragma unroll
            for (int ky = 0; ky < 3; ++ky) {
                #pragma unroll
                for (int kx = 0; kx < 3; ++kx) {
                    int t = ky * 3 + kx;
                    uint64_t s = buf[(2 * q + ky) * PW + 2 * tx + kx];
                    slo[t] = (uint32_t)s;
                    shi[t] = (uint32_t)(s >> 32);
                }
            }
            uint32_t mr = (ho > 0) ? 0xFFFFFFFFu : 0u;
            uint32_t mc = (tx > 0) ? 0xFFFFFFFFu : 0u;
            uint32_t mb = mr & mc;
            int base = 64 * (ho > 0 ? 3 : 2) * (tx > 0 ? 3 : 2);

            float* op = out + (((size_t)n * CO) * HO + ho) * WO + tx;

            #pragma unroll 4
            for (int co = 0; co < CO; ++co) {
                const uint64_t* wrow = sw + co * 9;
                int acc = 0;
                #pragma unroll
                for (int t = 0; t < 9; ++t) {
                    uint64_t wv = wrow[t];     // warp-uniform broadcast LDS
                    uint32_t wl = (uint32_t)wv;
                    uint32_t wh = (uint32_t)(wv >> 32);
                    if (t == 0) {
                        acc += __popc((slo[t] ^ wl) & mb);
                        acc += __popc((shi[t] ^ wh) & mb);
                    } else if (t == 1 || t == 2) {
                        acc += __popc((slo[t] ^ wl) & mr);
                        acc += __popc((shi[t] ^ wh) & mr);
                    } else if (t == 3 || t == 6) {
                        acc += __popc((slo[t] ^ wl) & mc);
                        acc += __popc((shi[t] ^ wh) & mc);
                    } else {
                        acc += __popc(slo[t] ^ wl);
                        acc += __popc(shi[t] ^ wh);
                    }
                }
                op[(size_t)co * (HO * WO)] = (float)(base - 2 * acc);
            }
        }
        __syncthreads();
    }
}

// ---------------------------------------------------------------------------
extern "C" void kernel_launch(void* const* d_in, const int* in_sizes, int n_in,
                              void* d_out, int out_size) {
    const float* x = (const float*)d_in[0];
    const float* w = (const float*)d_in[1];
    float* out = (float*)d_out;

    pack_w_kernel<<<16, 64>>>(w);
    qconv_pipe_kernel<<<dim3(16, NB), 256>>>(x, out);
}

// round 13
// speedup vs baseline: 1.0593x; 1.0386x over previous
#include <cuda_runtime.h>
#include <cstdint>

// Problem dims
#define NB 32
#define C  64
#define H  128
#define W  128
#define CO 64
#define HO 64
#define WO 64

// Packed weight sign bits: g_wpack[co*9 + ky*3 + kx]
__device__ uint64_t g_wpack[CO * 9];

// ---------------------------------------------------------------------------
// Kernel 1: pack w sign bits (tiny; 16 blocks x 36 words).
// ---------------------------------------------------------------------------
__global__ __launch_bounds__(64) void pack_w_kernel(const float* __restrict__ w) {
    int t = blockIdx.x * 36 + threadIdx.x;
    if (threadIdx.x < 36 && t < CO * 9) {
        int co = t / 9;
        int k  = t - co * 9;
        uint32_t lo = 0, hi = 0;
        #pragma unroll 8
        for (int ci = 0; ci < 32; ++ci)
            lo |= (uint32_t)(w[(size_t)(co * 64 + ci) * 9 + k] >= 0.0f) << ci;
        #pragma unroll 8
        for (int ci = 0; ci < 32; ++ci)
            hi |= (uint32_t)(w[(size_t)(co * 64 + ci + 32) * 9 + k] >= 0.0f) << ci;
        g_wpack[t] = (uint64_t)lo | ((uint64_t)hi << 32);
    }
}

// ---------------------------------------------------------------------------
// Kernel 2: FUSED pack + conv, 2 pixels/thread (R10 base + R8 idea done
// right: 256-thread blocks keep occupancy, 4 acc chains per thread give the
// warp enough ILP to cover LDS latency and break the serial IADD chain).
// Grid (16, NB) = 512 blocks. Block = 4 output rows x 64 wo x 64 co,
// 9-row x 129-word patch (x re-read 1.125x vs 1.25x before).
// Thread (tx=wo, ty=0..3): q=ty&1 -> rows ho0+q (A) and ho0+q+2 (B);
// coh=(ty>>1)*32 -> 32 c_out. Weight LDS amortized over 2 pixels.
// ---------------------------------------------------------------------------
__global__ __launch_bounds__(256) void qconv_fused_kernel(const float* __restrict__ x,
                                                          float* __restrict__ out) {
    const int PW = 132;
    __shared__ uint64_t sw[CO * 9];        // 4608 B
    __shared__ uint64_t sp[9 * PW];        // 9504 B

    int tid = threadIdx.x;
    int n   = blockIdx.y;
    int ho0 = blockIdx.x * 4;
    int iy0 = 2 * ho0 - 1;

    // ---- Phase 1: pack 9x129 patch straight from x floats ----
    for (int i = tid; i < 9 * 129; i += 256) {
        int r  = i / 129;
        int cx = i - r * 129;
        int iy = iy0 + r;
        int ix = cx - 1;
        uint32_t lo = 0, hi = 0;
        if (iy >= 0 && ix >= 0) {          // upper bounds always in range
            const float* p = x + (size_t)n * C * (H * W) + iy * W + ix;
            #pragma unroll 16
            for (int c = 0; c < 32; ++c) {
                lo |= (uint32_t)(__ldcs(p + (size_t)c * (H * W)) >= 0.0f) << c;
                hi |= (uint32_t)(__ldcs(p + (size_t)(c + 32) * (H * W)) >= 0.0f) << c;
            }
        }
        sp[r * PW + cx] = (uint64_t)lo | ((uint64_t)hi << 32);
    }
    for (int i = tid; i < CO * 9; i += 256)
        sw[i] = g_wpack[i];
    __syncthreads();

    // ---- Phase 2: compute, 2 pixels x 32 co per thread ----
    int tx  = tid & 63;                    // wo
    int ty  = tid >> 6;                    // 0..3
    int q   = ty & 1;                      // row parity within block
    int coh = (ty >> 1) * 32;              // co half
    int hoA = ho0 + q;                     // pixel A row (may be 0)
    // pixel B row = hoA + 2 (always >= 2 -> never row-clipped)

    uint32_t aLo[9], aHi[9], bLo[9], bHi[9];
    #pragma unroll
    for (int ky = 0; ky < 3; ++ky) {
        #pragma unroll
        for (int kx = 0; kx < 3; ++kx) {
            int t = ky * 3 + kx;
            uint64_t sa = sp[(2 * q + ky)     * PW + 2 * tx + kx];
            uint64_t sb = sp[(2 * q + 4 + ky) * PW + 2 * tx + kx];
            aLo[t] = (uint32_t)sa;  aHi[t] = (uint32_t)(sa >> 32);
            bLo[t] = (uint32_t)sb;  bHi[t] = (uint32_t)(sb >> 32);
        }
    }
    uint32_t mr = (hoA > 0) ? 0xFFFFFFFFu : 0u;   // A: ky==0 taps
    uint32_t mc = (tx  > 0) ? 0xFFFFFFFFu : 0u;   // kx==0 taps (A and B)
    uint32_t mb = mr & mc;
    int cw    = (tx > 0 ? 3 : 2);
    int baseA = 64 * (hoA > 0 ? 3 : 2) * cw;
    int baseB = 64 * 3 * cw;

    float* opA = out + (((size_t)n * CO + coh) * HO + hoA) * WO + tx;
    float* opB = opA + 2 * WO;
    const uint64_t* wbase = sw + coh * 9;

    #pragma unroll 2
    for (int co = 0; co < 32; ++co) {
        const uint64_t* wrow = wbase + co * 9;
        // 4 independent accumulator chains (A-lo, A-hi, B-lo, B-hi)
        int aA0 = 0, aA1 = 0, aB0 = 0, aB1 = 0;
        #pragma unroll
        for (int t = 0; t < 9; ++t) {
            uint64_t wv = wrow[t];                // warp-uniform broadcast LDS
            uint32_t wl = (uint32_t)wv;
            uint32_t wh = (uint32_t)(wv >> 32);
            if (t == 0) {
                aA0 += __popc((aLo[t] ^ wl) & mb);
                aA1 += __popc((aHi[t] ^ wh) & mb);
                aB0 += __popc((bLo[t] ^ wl) & mc);
                aB1 += __popc((bHi[t] ^ wh) & mc);
            } else if (t == 1 || t == 2) {
                aA0 += __popc((aLo[t] ^ wl) & mr);
                aA1 += __popc((aHi[t] ^ wh) & mr);
                aB0 += __popc(bLo[t] ^ wl);
                aB1 += __popc(bHi[t] ^ wh);
            } else if (t == 3 || t == 6) {
                aA0 += __popc((aLo[t] ^ wl) & mc);
                aA1 += __popc((aHi[t] ^ wh) & mc);
                aB0 += __popc((bLo[t] ^ wl) & mc);
                aB1 += __popc((bHi[t] ^ wh) & mc);
            } else {
                aA0 += __popc(aLo[t] ^ wl);
                aA1 += __popc(aHi[t] ^ wh);
                aB0 += __popc(bLo[t] ^ wl);
                aB1 += __popc(bHi[t] ^ wh);
            }
        }
        size_t off = (size_t)co * (HO * WO);
        opA[off] = (float)(baseA - 2 * (aA0 + aA1));
        opB[off] = (float)(baseB - 2 * (aB0 + aB1));
    }
}

// ---------------------------------------------------------------------------
extern "C" void kernel_launch(void* const* d_in, const int* in_sizes, int n_in,
                              void* d_out, int out_size) {
    const float* x = (const float*)d_in[0];
    const float* w = (const float*)d_in[1];
    float* out = (float*)d_out;

    pack_w_kernel<<<16, 64>>>(w);
    qconv_fused_kernel<<<dim3(16, NB), 256>>>(x, out);
}